// round 5
// baseline (speedup 1.0000x reference)
#include <cuda_runtime.h>
#include <math.h>

#define BB 2
#define N1 384
#define N2 384
#define DD 128
#define HH 128
#define LL 3
#define NF 54
#define NBLK 148

// ---------------- scratch (device globals; no allocation) ----------------
static __device__ float g_h1g[BB*N1*DD];
static __device__ float g_h2g[BB*N2*DD];
static __device__ float g_hX [2*BB*N1*DD];   // ping-pong h
static __device__ float g_hAX[2*BB*N1*DD];   // ping-pong hA
static __device__ float g_P  [BB*N1*N1];
static __device__ float g_att[BB*N1*N1];
static __device__ float g_p1 [5*BB*N1*HH];
static __device__ float g_p2 [5*BB*N2*HH];
static __device__ float g_WA [LL*DD*DD];
static __device__ float g_bA [LL*DD];
static __device__ float g_pec[576];
static __device__ float g_pev[576];

static __device__ unsigned g_cnt = 0;
static __device__ volatile unsigned g_gen = 0;

__device__ __forceinline__ float sigmoidf_(float x){ return 1.f/(1.f+__expf(-x)); }

// software grid barrier: all NBLK blocks are resident (1 wave) by construction
__device__ __forceinline__ void gridbar(){
    __syncthreads();
    if (threadIdx.x == 0){
        unsigned gen = g_gen;
        __threadfence();
        if (atomicAdd(&g_cnt, 1u) == NBLK - 1u){
            atomicExch(&g_cnt, 0u);
            __threadfence();
            g_gen = gen + 1u;
        } else {
            while (g_gen == gen) __nanosleep(32);
        }
        __threadfence();
    }
    __syncthreads();
}

__global__ __launch_bounds__(256) void k_persist(
    const float* __restrict__ h1,   const float* __restrict__ h2,
    const float* __restrict__ adj,  const float* __restrict__ dmv,
    const float* __restrict__ c1,   const float* __restrict__ c2,
    const float* __restrict__ eps,  const float* __restrict__ sig,
    const float* __restrict__ delta_uff,
    const float* __restrict__ val1, const float* __restrict__ val2,
    const float* __restrict__ nmm1, const float* __restrict__ nmm2,
    const float* __restrict__ nodeW,
    const float* __restrict__ gatW, const float* __restrict__ gatWb,
    const float* __restrict__ gatA,
    const float* __restrict__ gW,   const float* __restrict__ gb,
    const float* __restrict__ pW1,  const float* __restrict__ pb1,
    const float* __restrict__ pW2,  const float* __restrict__ pb2,
    const float* __restrict__ vdwc, const float* __restrict__ duff,
    const float* __restrict__ iW1,  const float* __restrict__ ib1,
    const float* __restrict__ iW2,  const float* __restrict__ ib2,
    float* __restrict__ out)
{
    __shared__ __align__(16) float SM[7208];
    int tid = threadIdx.x;
    int bid = blockIdx.x;
    int d = tid & 127, half = tid >> 7;
    int w = tid >> 5, lane = tid & 31;

    // ======== phase 0: WA=W@A, bA=Wb@A (items 0..191) + node proj (items 192..383) ========
    for (int it = bid; it < 384; it += NBLK){
        if (it < 192){
            int l = it/64, kk = (it & 63)*2 + half;
            const float* Wr = gatW + (l*DD + kk)*DD;
            const float* Al = gatA + l*DD*DD;
            float acc = 0.f;
            #pragma unroll 4
            for (int m = 0; m < DD; m++) acc += Wr[m]*Al[m*DD + d];
            g_WA[(l*DD + kk)*DD + d] = acc;
            if ((it & 63) == 0 && half == 0){
                float bacc = 0.f;
                #pragma unroll 4
                for (int m = 0; m < DD; m++) bacc += gatWb[l*DD + m]*Al[m*DD + d];
                g_bA[l*DD + d] = bacc;
            }
        } else {
            int r0 = (it - 192)*8;
            bool lig = (r0 < BB*N1);
            const float* src = lig ? (h1 + r0*NF) : (h2 + (r0 - BB*N1)*NF);
            float* sx = SM;   // [8][NF]
            __syncthreads();
            for (int idx = tid; idx < 8*NF; idx += 256) sx[idx] = src[idx];
            __syncthreads();
            float acc[4] = {0.f,0.f,0.f,0.f};
            #pragma unroll 2
            for (int k = 0; k < NF; k++){
                float wv = nodeW[k*DD + d];
                #pragma unroll
                for (int q = 0; q < 4; q++) acc[q] += sx[(half*4 + q)*NF + k]*wv;
            }
            float* dst = lig ? (g_h1g + r0*DD) : (g_h2g + (r0 - BB*N1)*DD);
            #pragma unroll
            for (int q = 0; q < 4; q++) dst[(half*4 + q)*DD + d] = acc[q];
        }
    }
    gridbar();

    // ======== phase 1: gat_h layer0 (0..95) + protein pair-proj (96..335) ========
    for (int it = bid; it < 336; it += NBLK){
        if (it < 96){
            int r0 = it*8;
            float* sx = SM;   // [8][128]
            __syncthreads();
            for (int idx = tid; idx < 8*DD; idx += 256) sx[idx] = g_h1g[r0*DD + idx];
            __syncthreads();
            float wb = gatWb[d], bav = g_bA[d];
            float h[4], ha[4];
            #pragma unroll
            for (int q = 0; q < 4; q++){ h[q] = wb; ha[q] = bav; }
            #pragma unroll 2
            for (int k = 0; k < DD; k++){
                float wv  = gatW[k*DD + d];
                float wav = g_WA[k*DD + d];
                #pragma unroll
                for (int q = 0; q < 4; q++){
                    h [q] += sx[(half*4 + q)*DD + k]*wv;
                    ha[q] += sx[(half*4 + q)*DD + k]*wav;
                }
            }
            #pragma unroll
            for (int q = 0; q < 4; q++){
                g_hX [(r0 + half*4 + q)*DD + d] = h [q];
                g_hAX[(r0 + half*4 + q)*DD + d] = ha[q];
            }
        } else {
            int p = it - 96;
            int m = p/48, r0 = (p % 48)*16;
            float* sx = SM;   // [16][128]
            __syncthreads();
            for (int idx = tid; idx < 16*DD; idx += 256) sx[idx] = g_h2g[r0*DD + idx];
            __syncthreads();
            const float* W = pW1 + m*2*DD*HH + DD*HH;   // protein half, no bias
            float acc[8];
            #pragma unroll
            for (int q = 0; q < 8; q++) acc[q] = 0.f;
            #pragma unroll 2
            for (int k = 0; k < DD; k++){
                float wv = W[k*HH + d];
                #pragma unroll
                for (int q = 0; q < 8; q++) acc[q] = fmaf(sx[(half*8 + q)*DD + k], wv, acc[q]);
            }
            #pragma unroll
            for (int q = 0; q < 8; q++) g_p2[(m*BB*N2 + r0 + half*8 + q)*HH + d] = acc[q];
        }
    }
    gridbar();

    // ======== GAT layers ========
    for (int l = 0; l < LL; l++){
        const float* hb  = g_hX  + (l & 1)*BB*N1*DD;
        const float* hab = g_hAX + (l & 1)*BB*N1*DD;

        // ---- P = hA @ h^T : 32x64 tiles, 144 items ----
        for (int it = bid; it < 144; it += NBLK){
            int kx = it % 6, jy = (it/6) % 12, b = it/72;
            int j0 = jy*32, k0 = kx*64;
            float* sA = SM;            // [64][36] (k-major, rows j)
            float* sB = SM + 64*36;    // [64][68] (k-major, rows k)
            int tx = tid & 15, ty = tid >> 4;
            float acc[2][4];
            #pragma unroll
            for (int r = 0; r < 2; r++)
                #pragma unroll
                for (int c = 0; c < 4; c++) acc[r][c] = 0.f;
            const float* baseA = hab + (b*N1 + j0)*DD;
            const float* baseB = hb  + (b*N1 + k0)*DD;
            for (int ks = 0; ks < 2; ks++){
                __syncthreads();
                #pragma unroll
                for (int q = 0; q < 2; q++){
                    int idx = tid + q*256;
                    int row = idx & 31, kq = idx >> 5;
                    float4 va = *(const float4*)(baseA + row*DD + ks*64 + kq*4);
                    sA[(kq*4+0)*36 + row] = va.x; sA[(kq*4+1)*36 + row] = va.y;
                    sA[(kq*4+2)*36 + row] = va.z; sA[(kq*4+3)*36 + row] = va.w;
                }
                #pragma unroll
                for (int q = 0; q < 4; q++){
                    int idx = tid + q*256;
                    int row = idx & 63, kq = idx >> 6;
                    float4 vb = *(const float4*)(baseB + row*DD + ks*64 + kq*4);
                    sB[(kq*4+0)*68 + row] = vb.x; sB[(kq*4+1)*68 + row] = vb.y;
                    sB[(kq*4+2)*68 + row] = vb.z; sB[(kq*4+3)*68 + row] = vb.w;
                }
                __syncthreads();
                #pragma unroll 8
                for (int kk = 0; kk < 64; kk++){
                    float2 av = *(const float2*)&sA[kk*36 + ty*2];
                    float4 bv = *(const float4*)&sB[kk*68 + tx*4];
                    acc[0][0] = fmaf(av.x, bv.x, acc[0][0]);
                    acc[0][1] = fmaf(av.x, bv.y, acc[0][1]);
                    acc[0][2] = fmaf(av.x, bv.z, acc[0][2]);
                    acc[0][3] = fmaf(av.x, bv.w, acc[0][3]);
                    acc[1][0] = fmaf(av.y, bv.x, acc[1][0]);
                    acc[1][1] = fmaf(av.y, bv.y, acc[1][1]);
                    acc[1][2] = fmaf(av.y, bv.z, acc[1][2]);
                    acc[1][3] = fmaf(av.y, bv.w, acc[1][3]);
                }
            }
            #pragma unroll
            for (int r = 0; r < 2; r++){
                float4 o = make_float4(acc[r][0], acc[r][1], acc[r][2], acc[r][3]);
                *(float4*)&g_P[(b*N1 + j0 + ty*2 + r)*N1 + k0 + tx*4] = o;
            }
        }
        gridbar();

        // ---- column softmax of e = P + P^T, masked by adj : 8 cols/item, 96 items ----
        for (int it = bid; it < 96; it += NBLK){
            int b = it/48, c0 = (it % 48)*8;
            float* sCol = SM;            // [384][9]
            float* sRow = SM + N1*9;     // [8][385]
            __syncthreads();
            for (int idx = tid; idx < N1*8; idx += 256){
                int r = idx >> 3, c = idx & 7;
                float p = g_P[(b*N1 + r)*N1 + c0 + c];
                float a = adj[(b*N1 + r)*N1 + c0 + c];
                sCol[r*9 + c] = (a > 0.f) ? p : -9e15f;
            }
            for (int idx = tid; idx < 8*N1; idx += 256){
                int cc = idx / N1, r = idx % N1;
                sRow[cc*385 + r] = g_P[(b*N1 + c0 + cc)*N1 + r];
            }
            __syncthreads();
            {   // warp w owns column w
                int cc = w;
                float ev[12];
                float mx = -INFINITY;
                #pragma unroll
                for (int t = 0; t < 12; t++){
                    int r = lane + t*32;
                    float e = sCol[r*9 + cc];
                    if (e > -8e15f) e += sRow[cc*385 + r];
                    ev[t] = e;
                    mx = fmaxf(mx, e);
                }
                #pragma unroll
                for (int o = 16; o; o >>= 1) mx = fmaxf(mx, __shfl_xor_sync(0xffffffffu, mx, o));
                float sum = 0.f;
                #pragma unroll
                for (int t = 0; t < 12; t++){
                    float x = __expf(ev[t] - mx);
                    ev[t] = x; sum += x;
                }
                #pragma unroll
                for (int o = 16; o; o >>= 1) sum += __shfl_xor_sync(0xffffffffu, sum, o);
                float inv = 1.f/sum;
                #pragma unroll
                for (int t = 0; t < 12; t++) sCol[(lane + t*32)*9 + cc] = ev[t]*inv;
            }
            __syncthreads();
            for (int idx = tid; idx < N1*8; idx += 256){
                int r = idx >> 3, c = idx & 7;
                float a = adj[(b*N1 + r)*N1 + c0 + c];
                g_att[(b*N1 + r)*N1 + c0 + c] = sCol[r*9 + c]*a;
            }
        }
        gridbar();

        // ---- fuse: h'=relu(att@h), gated residual, next-layer h/hA : 96 items ----
        for (int it = bid; it < 96; it += NBLK){
            int r0 = it*8;
            int b  = r0 / N1;
            float* s_att = SM;            // [8][384]
            float* s_g   = SM + 3072;     // [8][128]
            float* sx    = SM + 4096;     // [8][128]
            float* s_c   = SM + 5120;     // [8]
            __syncthreads();
            for (int idx = tid; idx < 8*N1; idx += 256) s_att[idx] = g_att[r0*N1 + idx];
            float xd[4];
            #pragma unroll
            for (int q = 0; q < 4; q++) xd[q] = g_h1g[(r0 + half*4 + q)*DD + d];
            __syncthreads();
            float hp[4] = {0.f,0.f,0.f,0.f};
            const float* hcol = hb + b*N1*DD + d;
            #pragma unroll 4
            for (int j = 0; j < N1; j++){
                float hv = hcol[j*DD];
                #pragma unroll
                for (int q = 0; q < 4; q++) hp[q] = fmaf(s_att[(half*4 + q)*N1 + j], hv, hp[q]);
            }
            float gw1 = gW[l*2*DD + d], gw2 = gW[l*2*DD + DD + d], gbv = gb[l];
            #pragma unroll
            for (int q = 0; q < 4; q++){
                hp[q] = fmaxf(hp[q], 0.f);
                s_g[(half*4 + q)*DD + d] = fmaf(xd[q], gw1, hp[q]*gw2);
            }
            __syncthreads();
            {   // warp w reduces row w
                float s = s_g[w*DD + lane] + s_g[w*DD + lane + 32]
                        + s_g[w*DD + lane + 64] + s_g[w*DD + lane + 96];
                #pragma unroll
                for (int o = 16; o; o >>= 1) s += __shfl_xor_sync(0xffffffffu, s, o);
                if (lane == 0) s_c[w] = sigmoidf_(s + gbv);
            }
            __syncthreads();
            #pragma unroll
            for (int q = 0; q < 4; q++){
                int row = half*4 + q;
                float coeff = s_c[row];
                float v = coeff*xd[q] + (1.f - coeff)*hp[q];
                g_h1g[(r0 + row)*DD + d] = v;
                sx[row*DD + d] = v;
            }
            if (l < LL-1){
                __syncthreads();
                int nl = l + 1;
                const float* W  = gatW + nl*DD*DD;
                const float* WA = g_WA + nl*DD*DD;
                float wb = gatWb[nl*DD + d], bav = g_bA[nl*DD + d];
                float hh2[4], ha[4];
                #pragma unroll
                for (int q = 0; q < 4; q++){ hh2[q] = wb; ha[q] = bav; }
                #pragma unroll 2
                for (int k = 0; k < DD; k++){
                    float wv  = W [k*DD + d];
                    float wav = WA[k*DD + d];
                    #pragma unroll
                    for (int q = 0; q < 4; q++){
                        hh2[q] += sx[(half*4 + q)*DD + k]*wv;
                        ha [q] += sx[(half*4 + q)*DD + k]*wav;
                    }
                }
                float* ho  = g_hX  + (nl & 1)*BB*N1*DD;
                float* hao = g_hAX + (nl & 1)*BB*N1*DD;
                #pragma unroll
                for (int q = 0; q < 4; q++){
                    ho [(r0 + half*4 + q)*DD + d] = hh2[q];
                    hao[(r0 + half*4 + q)*DD + d] = ha[q];
                }
            }
        }
        gridbar();
    }

    // ======== ligand pair projections: 240 items ========
    for (int it = bid; it < 240; it += NBLK){
        int m = it/48, r0 = (it % 48)*16;
        float* sx = SM;   // [16][128]
        __syncthreads();
        for (int idx = tid; idx < 16*DD; idx += 256) sx[idx] = g_h1g[r0*DD + idx];
        __syncthreads();
        const float* W = pW1 + m*2*DD*HH;
        float bias = pb1[m*HH + d];
        float acc[8];
        #pragma unroll
        for (int q = 0; q < 8; q++) acc[q] = bias;
        #pragma unroll 2
        for (int k = 0; k < DD; k++){
            float wv = W[k*HH + d];
            #pragma unroll
            for (int q = 0; q < 8; q++) acc[q] = fmaf(sx[(half*8 + q)*DD + k], wv, acc[q]);
        }
        #pragma unroll
        for (int q = 0; q < 8; q++) g_p1[(m*BB*N1 + r0 + half*8 + q)*HH + d] = acc[q];
    }
    gridbar();

    // ======== pair energies: 576 items (16i x 32j tiles) ========
    {
        float* s_p1  = SM;           // [16][132]
        float* s_p2  = SM + 2112;    // [32][132]
        float* s_w2  = SM + 6336;    // [5][128]
        float* s_b2v = SM + 6976;    // [5]
        float* s_red = SM + 6984;    // [16]
        __syncthreads();
        for (int idx = tid; idx < 5*DD; idx += 256) s_w2[idx] = pW2[idx];
        if (tid < 5) s_b2v[tid] = pb2[tid];
        float vdwc2 = vdwc[0]*vdwc[0];
        for (int it = bid; it < 576; it += NBLK){
            int bix = it % 12, biy = it / 12;
            int r0 = biy*16;
            int b  = r0 / N1;
            int i1 = r0 % N1;
            int j0 = bix*32;
            int j  = lane;
            int ia = w*2;
            float acc[2][5];
            #pragma unroll
            for (int q = 0; q < 2; q++)
                #pragma unroll
                for (int m = 0; m < 5; m++) acc[q][m] = 0.f;
            for (int m = 0; m < 5; m++){
                __syncthreads();
                #pragma unroll
                for (int q = 0; q < 2; q++){
                    int idx = tid + q*256;
                    int row = idx >> 5, q4 = idx & 31;
                    float4 v = *(const float4*)(g_p1 + (size_t)(m*BB*N1 + r0 + row)*HH + q4*4);
                    *(float4*)&s_p1[row*132 + q4*4] = v;
                }
                #pragma unroll
                for (int q = 0; q < 4; q++){
                    int idx = tid + q*256;
                    int row = idx >> 5, q4 = idx & 31;
                    float4 v = *(const float4*)(g_p2 + (size_t)(m*BB*N2 + b*N2 + j0 + row)*HH + q4*4);
                    *(float4*)&s_p2[row*132 + q4*4] = v;
                }
                __syncthreads();
                float a0 = 0.f, a1 = 0.f;
                #pragma unroll
                for (int hv = 0; hv < 32; hv++){
                    float4 w4  = *(const float4*)&s_w2[m*128 + hv*4];
                    float4 p2v = *(const float4*)&s_p2[j*132 + hv*4];
                    float4 pa  = *(const float4*)&s_p1[ia*132 + hv*4];
                    float4 pb  = *(const float4*)&s_p1[(ia+1)*132 + hv*4];
                    a0 = fmaf(fmaxf(pa.x + p2v.x, 0.f), w4.x, a0);
                    a0 = fmaf(fmaxf(pa.y + p2v.y, 0.f), w4.y, a0);
                    a0 = fmaf(fmaxf(pa.z + p2v.z, 0.f), w4.z, a0);
                    a0 = fmaf(fmaxf(pa.w + p2v.w, 0.f), w4.w, a0);
                    a1 = fmaf(fmaxf(pb.x + p2v.x, 0.f), w4.x, a1);
                    a1 = fmaf(fmaxf(pb.y + p2v.y, 0.f), w4.y, a1);
                    a1 = fmaf(fmaxf(pb.z + p2v.z, 0.f), w4.z, a1);
                    a1 = fmaf(fmaxf(pb.w + p2v.w, 0.f), w4.w, a1);
                }
                acc[0][m] = a0; acc[1][m] = a1;
            }
            float ec = 0.f, ev = 0.f;
            int jl = j0 + j;
            float c2v = c2[b*N2 + jl], v2v = val2[b*N2 + jl], n2v = nmm2[b*N2 + jl];
            #pragma unroll
            for (int q = 0; q < 2; q++){
                int il = i1 + ia + q;
                float v0 = acc[q][0] + s_b2v[0];
                float v1 = acc[q][1] + s_b2v[1];
                float v2 = acc[q][2] + s_b2v[2];
                float v3 = acc[q][3] + s_b2v[3];
                float v4 = acc[q][4] + s_b2v[4];
                int pix = (b*N1 + il)*N2 + jl;
                const float* dv = dmv + (size_t)pix*3;
                float dx = dv[0], dy = dv[1], dz = dv[2];
                float dm = sqrtf(dx*dx + dy*dy + dz*dz + 1e-10f);
                if (dm < 0.5f) dm = 1e10f;
                float l2dm = __log2f(dm);
                float cA  = sigmoidf_(v0);
                float cN  = 2.f*sigmoidf_(v1) + 1.f;
                float q12 = c1[b*N1 + il]*c2v;
                float e_c = cA*q12*exp2f(-cN*l2dm);
                e_c *= val1[b*N1 + il]*v2v;
                e_c = fminf(fmaxf(e_c, -100.f), 100.f);
                float vAv = (0.6f*sigmoidf_(v2) + 0.7f)*vdwc2*eps[pix];
                float vBv = tanhf(v3)*0.6f + 0.7f;
                float vNv = 2.f*sigmoidf_(v4) + 5.f;
                float dm0 = sig[pix]*vBv;
                if (dm0 < 1e-4f) dm0 = 1.f;
                float r  = exp2f(vNv*(__log2f(dm0) - l2dm));
                float e_v = vAv*(r*r - 2.f*r);
                e_v *= nmm1[b*N1 + il]*n2v;
                e_v = fminf(e_v, 100.f);
                ec += e_c; ev += e_v;
            }
            #pragma unroll
            for (int o = 16; o; o >>= 1){
                ec += __shfl_xor_sync(0xffffffffu, ec, o);
                ev += __shfl_xor_sync(0xffffffffu, ev, o);
            }
            if (lane == 0){ s_red[w] = ec; s_red[8 + w] = ev; }
            __syncthreads();
            if (tid == 0){
                float tec = 0.f, tev = 0.f;
                #pragma unroll
                for (int qq = 0; qq < 8; qq++){ tec += s_red[qq]; tev += s_red[8 + qq]; }
                g_pec[biy*12 + bix] = tec;
                g_pev[biy*12 + bix] = tev;
            }
        }
    }
    gridbar();

    // ======== finalize: 2 items ========
    for (int it = bid; it < BB; it += NBLK){
        int b = it;
        float* s2    = SM;           // [2][128]
        float* s_hs  = SM + 256;     // [128]
        float* s_red = SM + 384;     // [256]
        float hs = 0.f;
        for (int i = half; i < N1; i += 2) hs += g_h1g[(b*N1 + i)*DD + d]*val1[b*N1 + i];
        s2[half*128 + d] = hs;
        __syncthreads();
        if (tid < 128) s_hs[d] = s2[d] + s2[128 + d];
        __syncthreads();
        float contrib = 0.f;
        if (tid < 128){
            float hid = ib1[d];
            #pragma unroll 4
            for (int k = 0; k < DD; k++) hid += s_hs[k]*iW1[k*HH + d];
            contrib = fmaxf(hid, 0.f)*iW2[d];
        }
        s_red[tid] = contrib;
        __syncthreads();
        for (int s = 128; s; s >>= 1){ if (tid < s) s_red[tid] += s_red[tid + s]; __syncthreads(); }
        float inter = s_red[0] + ib2[0];
        __syncthreads();
        float tec = 0.f;
        for (int q = tid; q < 288; q += 256) tec += g_pec[b*288 + q];
        s_red[tid] = tec;
        __syncthreads();
        for (int s = 128; s; s >>= 1){ if (tid < s) s_red[tid] += s_red[tid + s]; __syncthreads(); }
        float tecs = s_red[0];
        __syncthreads();
        float tev = 0.f;
        for (int q = tid; q < 288; q += 256) tev += g_pev[b*288 + q];
        s_red[tid] = tev;
        __syncthreads();
        for (int s = 128; s; s >>= 1){ if (tid < s) s_red[tid] += s_red[tid + s]; __syncthreads(); }
        if (tid == 0){
            out[b*4 + 0] = tecs;
            out[b*4 + 1] = s_red[0];
            out[b*4 + 2] = duff[0]*duff[0]*delta_uff[b];
            out[b*4 + 3] = inter;
        }
        __syncthreads();
    }
}

// ---------------- launch ----------------
// d_in follows setup_inputs() dict insertion order:
//   0:h1 1:h2 2:adj1 3:dmv 4:charge1 5:charge2 6:vdw_epsilon 7:vdw_sigma
//   8:delta_uff 9:valid1 10:valid2 11:no_metal1 12:no_metal2 13:node_W
//   14:gat_W 15:gat_Wb 16:gat_A 17:gat_gW 18:gat_gb 19:pair_W1 20:pair_b1
//   21:pair_W2 22:pair_b2 23:vdw_coeff 24:duff_coeff 25:int_W1 26:int_b1
//   27:int_W2 28:int_b2
extern "C" void kernel_launch(void* const* d_in, const int* in_sizes, int n_in,
                              void* d_out, int out_size){
    k_persist<<<NBLK, 256>>>(
        (const float*)d_in[0],  (const float*)d_in[1],  (const float*)d_in[2],
        (const float*)d_in[3],  (const float*)d_in[4],  (const float*)d_in[5],
        (const float*)d_in[6],  (const float*)d_in[7],  (const float*)d_in[8],
        (const float*)d_in[9],  (const float*)d_in[10], (const float*)d_in[11],
        (const float*)d_in[12], (const float*)d_in[13], (const float*)d_in[14],
        (const float*)d_in[15], (const float*)d_in[16], (const float*)d_in[17],
        (const float*)d_in[18], (const float*)d_in[19], (const float*)d_in[20],
        (const float*)d_in[21], (const float*)d_in[22], (const float*)d_in[23],
        (const float*)d_in[24], (const float*)d_in[25], (const float*)d_in[26],
        (const float*)d_in[27], (const float*)d_in[28],
        (float*)d_out);
}

// round 6
// speedup vs baseline: 1.0446x; 1.0446x over previous
#include <cuda_runtime.h>
#include <math.h>

#define BB 2
#define N1 384
#define N2 384
#define DD 128
#define HH 128
#define LL 3
#define NF 54

// ---------------- scratch (device globals; no allocation) ----------------
static __device__ float g_h1g[BB*N1*DD];
static __device__ float g_h2g[BB*N2*DD];
static __device__ float g_hX [2*BB*N1*DD];   // ping-pong h
static __device__ float g_hAX[2*BB*N1*DD];   // ping-pong hA
static __device__ float g_P  [BB*N1*N1];
static __device__ float g_PT [BB*N1*N1];
static __device__ float g_m  [BB*N1];
static __device__ float g_iz [BB*N1];
static __device__ float g_p1 [5*BB*N1*HH];
static __device__ float g_p2 [5*BB*N2*HH];
static __device__ float g_WA [LL*DD*DD];
static __device__ float g_bA [LL*DD];
static __device__ float g_pec[576];
static __device__ float g_pev[576];

__device__ __forceinline__ float sigmoidf_(float x){ return 1.f/(1.f+__expf(-x)); }

// ---------------- fused: WA=W@A, bA=Wb@A  +  node projection ----------------
__global__ __launch_bounds__(128) void k_pre_node(const float* __restrict__ W,
                                                  const float* __restrict__ Wb,
                                                  const float* __restrict__ A,
                                                  const float* __restrict__ h1,
                                                  const float* __restrict__ h2,
                                                  const float* __restrict__ nW){
    int bi = blockIdx.x, d = threadIdx.x;
    if (bi < LL*DD){
        int l = bi / DD, k = bi % DD;
        __shared__ float sw[DD];
        __shared__ float sb[DD];
        sw[d] = W[(l*DD + k)*DD + d];
        if (k == 0) sb[d] = Wb[l*DD + d];
        __syncthreads();
        const float* Al = A + l*DD*DD;
        float acc = 0.f;
        #pragma unroll 4
        for (int m = 0; m < DD; m++) acc += sw[m]*Al[m*DD + d];
        g_WA[(l*DD + k)*DD + d] = acc;
        if (k == 0){
            float bacc = 0.f;
            #pragma unroll 4
            for (int m = 0; m < DD; m++) bacc += sb[m]*Al[m*DD + d];
            g_bA[l*DD + d] = bacc;
        }
    } else {
        int r0 = (bi - LL*DD)*4;
        __shared__ float sx[4][NF];
        bool lig = (r0 < BB*N1);
        const float* src = lig ? (h1 + r0*NF) : (h2 + (r0 - BB*N1)*NF);
        for (int idx = d; idx < 4*NF; idx += 128) ((float*)sx)[idx] = src[idx];
        __syncthreads();
        float acc[4] = {0.f,0.f,0.f,0.f};
        #pragma unroll 2
        for (int k = 0; k < NF; k++){
            float wv = nW[k*DD + d];
            #pragma unroll
            for (int ii = 0; ii < 4; ii++) acc[ii] += sx[ii][k]*wv;
        }
        float* dst = lig ? (g_h1g + r0*DD) : (g_h2g + (r0 - BB*N1)*DD);
        #pragma unroll
        for (int ii = 0; ii < 4; ii++) dst[ii*DD + d] = acc[ii];
    }
}

// ---------------- stage2: gat_h layer0 (96 blocks) + protein pair-proj (240 blocks) ----------------
__global__ __launch_bounds__(128) void k_stage2(const float* __restrict__ gatW,
                                                const float* __restrict__ gatWb,
                                                const float* __restrict__ W1){
    int bi = blockIdx.x, d = threadIdx.x;
    __shared__ float sx[16][DD];
    if (bi < 96){
        int r0 = bi*8;
        #pragma unroll
        for (int ii = 0; ii < 8; ii++) sx[ii][d] = g_h1g[(r0 + ii)*DD + d];
        __syncthreads();
        float wb = gatWb[d], bav = g_bA[d];
        float h[8], ha[8];
        #pragma unroll
        for (int ii = 0; ii < 8; ii++){ h[ii] = wb; ha[ii] = bav; }
        #pragma unroll 2
        for (int k = 0; k < DD; k++){
            float wv  = gatW[k*DD + d];
            float wav = g_WA[k*DD + d];
            #pragma unroll
            for (int ii = 0; ii < 8; ii++){
                h [ii] += sx[ii][k]*wv;
                ha[ii] += sx[ii][k]*wav;
            }
        }
        #pragma unroll
        for (int ii = 0; ii < 8; ii++){
            g_hX [(r0 + ii)*DD + d] = h [ii];
            g_hAX[(r0 + ii)*DD + d] = ha[ii];
        }
    } else {
        int pi = bi - 96;
        int m  = pi / 48;
        int r0 = (pi % 48)*16;
        #pragma unroll
        for (int ii = 0; ii < 16; ii++) sx[ii][d] = g_h2g[(r0 + ii)*DD + d];
        __syncthreads();
        const float* W = W1 + m*2*DD*HH + DD*HH;   // protein half, no bias
        float acc[16];
        #pragma unroll
        for (int ii = 0; ii < 16; ii++) acc[ii] = 0.f;
        #pragma unroll 2
        for (int k = 0; k < DD; k++){
            float wv = W[k*HH + d];
            #pragma unroll
            for (int ii = 0; ii < 16; ii++) acc[ii] = fmaf(sx[ii][k], wv, acc[ii]);
        }
        #pragma unroll
        for (int ii = 0; ii < 16; ii++) g_p2[(m*BB*N2 + r0 + ii)*HH + d] = acc[ii];
    }
}

// ---------------- P = hA @ h^T (and P^T) : 32x64 tiles, 144 blocks ----------------
__global__ __launch_bounds__(256) void k_e(int cur){
    const float* hb  = g_hX  + cur*BB*N1*DD;
    const float* hab = g_hAX + cur*BB*N1*DD;
    int b = blockIdx.z, j0 = blockIdx.y*32, k0 = blockIdx.x*64;
    __shared__ float sA[64][36];
    __shared__ float sB[64][68];
    int tid = threadIdx.x;
    int tx = tid & 15, ty = tid >> 4;
    float acc[2][4];
    #pragma unroll
    for (int r = 0; r < 2; r++)
        #pragma unroll
        for (int c = 0; c < 4; c++) acc[r][c] = 0.f;
    const float* baseA = hab + (b*N1 + j0)*DD;
    const float* baseB = hb  + (b*N1 + k0)*DD;
    for (int ks = 0; ks < 2; ks++){
        __syncthreads();
        #pragma unroll
        for (int q = 0; q < 2; q++){
            int idx = tid + q*256;
            int row = idx & 31, kq = idx >> 5;
            float4 va = *(const float4*)(baseA + row*DD + ks*64 + kq*4);
            sA[kq*4+0][row] = va.x; sA[kq*4+1][row] = va.y;
            sA[kq*4+2][row] = va.z; sA[kq*4+3][row] = va.w;
        }
        #pragma unroll
        for (int q = 0; q < 4; q++){
            int idx = tid + q*256;
            int row = idx & 63, kq = idx >> 6;
            float4 vb = *(const float4*)(baseB + row*DD + ks*64 + kq*4);
            sB[kq*4+0][row] = vb.x; sB[kq*4+1][row] = vb.y;
            sB[kq*4+2][row] = vb.z; sB[kq*4+3][row] = vb.w;
        }
        __syncthreads();
        #pragma unroll 8
        for (int kk = 0; kk < 64; kk++){
            float2 av = *(const float2*)&sA[kk][ty*2];
            float4 bv = *(const float4*)&sB[kk][tx*4];
            acc[0][0] = fmaf(av.x, bv.x, acc[0][0]);
            acc[0][1] = fmaf(av.x, bv.y, acc[0][1]);
            acc[0][2] = fmaf(av.x, bv.z, acc[0][2]);
            acc[0][3] = fmaf(av.x, bv.w, acc[0][3]);
            acc[1][0] = fmaf(av.y, bv.x, acc[1][0]);
            acc[1][1] = fmaf(av.y, bv.y, acc[1][1]);
            acc[1][2] = fmaf(av.y, bv.z, acc[1][2]);
            acc[1][3] = fmaf(av.y, bv.w, acc[1][3]);
        }
    }
    #pragma unroll
    for (int r = 0; r < 2; r++){
        float4 o = make_float4(acc[r][0], acc[r][1], acc[r][2], acc[r][3]);
        *(float4*)&g_P[(b*N1 + j0 + ty*2 + r)*N1 + k0 + tx*4] = o;
    }
    #pragma unroll
    for (int c = 0; c < 4; c++){
        float2 o = make_float2(acc[0][c], acc[1][c]);
        *(float2*)&g_PT[(b*N1 + k0 + tx*4 + c)*N1 + j0 + ty*2] = o;
    }
}

// ---------------- column stats via symmetry: m[j], invZ[j] from row j of e ----------------
__global__ __launch_bounds__(256) void k_stats(const float* __restrict__ adj){
    int w = threadIdx.x >> 5, lane = threadIdx.x & 31;
    int rg = blockIdx.x*8 + w;                 // global row 0..767
    const float* pr  = g_P  + (size_t)rg*N1;
    const float* ptr = g_PT + (size_t)rg*N1;
    const float* ar  = adj  + (size_t)rg*N1;
    float ev[12];
    float mx = -INFINITY;
    #pragma unroll
    for (int t = 0; t < 12; t++){
        int i = lane + t*32;
        float a = ar[i];
        float e = (a > 0.f) ? (pr[i] + ptr[i]) : -9e15f;
        ev[t] = e;
        mx = fmaxf(mx, e);
    }
    #pragma unroll
    for (int o = 16; o; o >>= 1) mx = fmaxf(mx, __shfl_xor_sync(0xffffffffu, mx, o));
    float sum = 0.f;
    #pragma unroll
    for (int t = 0; t < 12; t++) sum += __expf(ev[t] - mx);
    #pragma unroll
    for (int o = 16; o; o >>= 1) sum += __shfl_xor_sync(0xffffffffu, sum, o);
    if (lane == 0){
        g_m [rg] = mx;
        g_iz[rg] = 1.f/sum;
    }
}

// ---------------- fuse: w on the fly, h'=relu(w@h), gate, then next h/hA or pair-proj ----------------
__global__ __launch_bounds__(256) void k_fuse(const float* __restrict__ adj,
                                              const float* __restrict__ gW,
                                              const float* __restrict__ gb,
                                              const float* __restrict__ gatW,
                                              const float* __restrict__ gatWb,
                                              const float* __restrict__ pW1,
                                              const float* __restrict__ pb1,
                                              int l){
    int r0 = blockIdx.x*8;
    int b  = r0 / N1;
    int tid = threadIdx.x;
    int d = tid & 127, half = tid >> 7;
    int w = tid >> 5, lane = tid & 31;
    const float* hb = g_hX + (l & 1)*BB*N1*DD;
    __shared__ float s_att[8][N1];
    __shared__ float s_mz[2][N1];
    __shared__ float s_g[8][DD];
    __shared__ float sx[8][DD];
    __shared__ float s_c[8];
    for (int idx = tid; idx < N1; idx += 256){
        s_mz[0][idx] = g_m [b*N1 + idx];
        s_mz[1][idx] = g_iz[b*N1 + idx];
    }
    __syncthreads();
    for (int idx = tid; idx < 8*N1; idx += 256){
        int ii = idx >> 8;            // idx / 384? no — compute properly
        ii = idx / N1;
        int j = idx - ii*N1;
        float a = adj[(r0 + ii)*N1 + j];
        float wv = 0.f;
        if (a > 0.f){
            float e = g_P[(size_t)(r0 + ii)*N1 + j] + g_PT[(size_t)(r0 + ii)*N1 + j];
            wv = __expf(e - s_mz[0][j])*s_mz[1][j]*a;
        }
        s_att[ii][j] = wv;
    }
    float xd[4];
    #pragma unroll
    for (int q = 0; q < 4; q++) xd[q] = g_h1g[(r0 + half*4 + q)*DD + d];
    __syncthreads();
    float hp[4] = {0.f,0.f,0.f,0.f};
    const float* hcol = hb + b*N1*DD + d;
    #pragma unroll 4
    for (int j = 0; j < N1; j++){
        float hv = hcol[j*DD];
        #pragma unroll
        for (int q = 0; q < 4; q++) hp[q] = fmaf(s_att[half*4 + q][j], hv, hp[q]);
    }
    float gw1 = gW[l*2*DD + d], gw2 = gW[l*2*DD + DD + d], gbv = gb[l];
    #pragma unroll
    for (int q = 0; q < 4; q++){
        hp[q] = fmaxf(hp[q], 0.f);
        s_g[half*4 + q][d] = fmaf(xd[q], gw1, hp[q]*gw2);
    }
    __syncthreads();
    {   // warp w reduces row w
        float s = s_g[w][lane] + s_g[w][lane+32] + s_g[w][lane+64] + s_g[w][lane+96];
        #pragma unroll
        for (int o = 16; o; o >>= 1) s += __shfl_xor_sync(0xffffffffu, s, o);
        if (lane == 0) s_c[w] = sigmoidf_(s + gbv);
    }
    __syncthreads();
    #pragma unroll
    for (int q = 0; q < 4; q++){
        int row = half*4 + q;
        float coeff = s_c[row];
        float v = coeff*xd[q] + (1.f - coeff)*hp[q];
        g_h1g[(r0 + row)*DD + d] = v;
        sx[row][d] = v;
    }
    __syncthreads();
    if (l < LL-1){
        int nl = l + 1;
        const float* W  = gatW + nl*DD*DD;
        const float* WA = g_WA + nl*DD*DD;
        float wb = gatWb[nl*DD + d], bav = g_bA[nl*DD + d];
        float hh2[4], ha[4];
        #pragma unroll
        for (int q = 0; q < 4; q++){ hh2[q] = wb; ha[q] = bav; }
        #pragma unroll 2
        for (int k = 0; k < DD; k++){
            float wv  = W [k*DD + d];
            float wav = WA[k*DD + d];
            #pragma unroll
            for (int q = 0; q < 4; q++){
                hh2[q] += sx[half*4 + q][k]*wv;
                ha [q] += sx[half*4 + q][k]*wav;
            }
        }
        float* ho  = g_hX  + (nl & 1)*BB*N1*DD;
        float* hao = g_hAX + (nl & 1)*BB*N1*DD;
        #pragma unroll
        for (int q = 0; q < 4; q++){
            ho [(r0 + half*4 + q)*DD + d] = hh2[q];
            hao[(r0 + half*4 + q)*DD + d] = ha[q];
        }
    } else {
        // final layer: compute ligand pair projections for these 8 rows, all 5 MLPs
        for (int m = 0; m < 5; m++){
            const float* W = pW1 + m*2*DD*HH;
            float bias = pb1[m*HH + d];
            float acc[4];
            #pragma unroll
            for (int q = 0; q < 4; q++) acc[q] = bias;
            #pragma unroll 2
            for (int k = 0; k < DD; k++){
                float wv = W[k*HH + d];
                #pragma unroll
                for (int q = 0; q < 4; q++) acc[q] = fmaf(sx[half*4 + q][k], wv, acc[q]);
            }
            #pragma unroll
            for (int q = 0; q < 4; q++)
                g_p1[(m*BB*N1 + r0 + half*4 + q)*HH + d] = acc[q];
        }
    }
}

// ---------------- pair energies: 16i x 32j tile, float4 mainloop ----------------
__global__ __launch_bounds__(256) void k_pair(const float* __restrict__ dmv,
                                              const float* __restrict__ c1,
                                              const float* __restrict__ c2,
                                              const float* __restrict__ eps,
                                              const float* __restrict__ sig,
                                              const float* __restrict__ val1,
                                              const float* __restrict__ val2,
                                              const float* __restrict__ nmm1,
                                              const float* __restrict__ nmm2,
                                              const float* __restrict__ W2,
                                              const float* __restrict__ b2,
                                              const float* __restrict__ vdwc){
    int bix = blockIdx.x;          // j tile 0..11
    int biy = blockIdx.y;          // i tile 0..47
    int r0  = biy*16;
    int b   = r0 / N1;
    int i1  = r0 % N1;
    int j0  = bix*32;
    __shared__ float s_p1[16][132];
    __shared__ float s_p2[32][132];
    __shared__ float s_w2[5][128];
    __shared__ float s_b2v[5];
    __shared__ float s_red[16];
    int tid = threadIdx.x, lane = tid & 31, w = tid >> 5;
    int j  = lane;
    int ia = w*2;
    for (int idx = tid; idx < 5*DD; idx += 256) s_w2[idx/DD][idx%DD] = W2[idx];
    if (tid < 5) s_b2v[tid] = b2[tid];
    float acc[2][5];
    #pragma unroll
    for (int q = 0; q < 2; q++)
        #pragma unroll
        for (int m = 0; m < 5; m++) acc[q][m] = 0.f;
    for (int m = 0; m < 5; m++){
        __syncthreads();
        #pragma unroll
        for (int q = 0; q < 2; q++){
            int idx = tid + q*256;
            int row = idx >> 5, q4 = idx & 31;
            float4 v = *(const float4*)(g_p1 + (size_t)(m*BB*N1 + r0 + row)*HH + q4*4);
            *(float4*)&s_p1[row][q4*4] = v;
        }
        #pragma unroll
        for (int q = 0; q < 4; q++){
            int idx = tid + q*256;
            int row = idx >> 5, q4 = idx & 31;
            float4 v = *(const float4*)(g_p2 + (size_t)(m*BB*N2 + b*N2 + j0 + row)*HH + q4*4);
            *(float4*)&s_p2[row][q4*4] = v;
        }
        __syncthreads();
        float a0 = 0.f, a1 = 0.f;
        #pragma unroll
        for (int hv = 0; hv < 32; hv++){
            float4 w4  = *(const float4*)&s_w2[m][hv*4];
            float4 p2v = *(const float4*)&s_p2[j][hv*4];
            float4 pa  = *(const float4*)&s_p1[ia][hv*4];
            float4 pb  = *(const float4*)&s_p1[ia+1][hv*4];
            a0 = fmaf(fmaxf(pa.x + p2v.x, 0.f), w4.x, a0);
            a0 = fmaf(fmaxf(pa.y + p2v.y, 0.f), w4.y, a0);
            a0 = fmaf(fmaxf(pa.z + p2v.z, 0.f), w4.z, a0);
            a0 = fmaf(fmaxf(pa.w + p2v.w, 0.f), w4.w, a0);
            a1 = fmaf(fmaxf(pb.x + p2v.x, 0.f), w4.x, a1);
            a1 = fmaf(fmaxf(pb.y + p2v.y, 0.f), w4.y, a1);
            a1 = fmaf(fmaxf(pb.z + p2v.z, 0.f), w4.z, a1);
            a1 = fmaf(fmaxf(pb.w + p2v.w, 0.f), w4.w, a1);
        }
        acc[0][m] = a0; acc[1][m] = a1;
    }
    float vdwc2 = vdwc[0]*vdwc[0];
    float ec = 0.f, ev = 0.f;
    int jl = j0 + j;
    float c2v = c2[b*N2 + jl], v2v = val2[b*N2 + jl], n2v = nmm2[b*N2 + jl];
    #pragma unroll
    for (int q = 0; q < 2; q++){
        int il = i1 + ia + q;
        float v0 = acc[q][0] + s_b2v[0];
        float v1 = acc[q][1] + s_b2v[1];
        float v2 = acc[q][2] + s_b2v[2];
        float v3 = acc[q][3] + s_b2v[3];
        float v4 = acc[q][4] + s_b2v[4];
        int pix = (b*N1 + il)*N2 + jl;
        const float* dv = dmv + (size_t)pix*3;
        float dx = dv[0], dy = dv[1], dz = dv[2];
        float dm = sqrtf(dx*dx + dy*dy + dz*dz + 1e-10f);
        if (dm < 0.5f) dm = 1e10f;
        float l2dm = __log2f(dm);
        float cA  = sigmoidf_(v0);
        float cN  = 2.f*sigmoidf_(v1) + 1.f;
        float q12 = c1[b*N1 + il]*c2v;
        float e_c = cA*q12*exp2f(-cN*l2dm);
        e_c *= val1[b*N1 + il]*v2v;
        e_c = fminf(fmaxf(e_c, -100.f), 100.f);
        float vAv = (0.6f*sigmoidf_(v2) + 0.7f)*vdwc2*eps[pix];
        float vBv = tanhf(v3)*0.6f + 0.7f;
        float vNv = 2.f*sigmoidf_(v4) + 5.f;
        float dm0 = sig[pix]*vBv;
        if (dm0 < 1e-4f) dm0 = 1.f;
        float r  = exp2f(vNv*(__log2f(dm0) - l2dm));
        float e_v = vAv*(r*r - 2.f*r);
        e_v *= nmm1[b*N1 + il]*n2v;
        e_v = fminf(e_v, 100.f);
        ec += e_c; ev += e_v;
    }
    #pragma unroll
    for (int o = 16; o; o >>= 1){
        ec += __shfl_xor_sync(0xffffffffu, ec, o);
        ev += __shfl_xor_sync(0xffffffffu, ev, o);
    }
    if (lane == 0){ s_red[w] = ec; s_red[8 + w] = ev; }
    __syncthreads();
    if (tid == 0){
        float tec = 0.f, tev = 0.f;
        #pragma unroll
        for (int qq = 0; qq < 8; qq++){ tec += s_red[qq]; tev += s_red[8 + qq]; }
        g_pec[biy*12 + bix] = tec;
        g_pev[biy*12 + bix] = tev;
    }
}

// ---------------- finalize ----------------
__global__ __launch_bounds__(DD) void k_final(const float* __restrict__ valid1,
                                              const float* __restrict__ delta_uff,
                                              const float* __restrict__ duff,
                                              const float* __restrict__ iW1,
                                              const float* __restrict__ ib1,
                                              const float* __restrict__ iW2,
                                              const float* __restrict__ ib2,
                                              float* __restrict__ out){
    int b = blockIdx.x, d = threadIdx.x;
    __shared__ float s_hs[DD];
    __shared__ float s_red[DD];
    float hs = 0.f;
    for (int i = 0; i < N1; i++) hs += g_h1g[(b*N1 + i)*DD + d]*valid1[b*N1 + i];
    s_hs[d] = hs;
    __syncthreads();
    float hid = ib1[d];
    #pragma unroll 4
    for (int k = 0; k < DD; k++) hid += s_hs[k]*iW1[k*HH + d];
    hid = fmaxf(hid, 0.f);
    s_red[d] = hid*iW2[d];
    __syncthreads();
    for (int s = 64; s; s >>= 1){ if (d < s) s_red[d] += s_red[d + s]; __syncthreads(); }
    float inter = s_red[0] + ib2[0];
    __syncthreads();
    float tec = 0.f;
    for (int q = d; q < 288; q += DD) tec += g_pec[b*288 + q];
    s_red[d] = tec;
    __syncthreads();
    for (int s = 64; s; s >>= 1){ if (d < s) s_red[d] += s_red[d + s]; __syncthreads(); }
    float tecs = s_red[0];
    __syncthreads();
    float tev = 0.f;
    for (int q = d; q < 288; q += DD) tev += g_pev[b*288 + q];
    s_red[d] = tev;
    __syncthreads();
    for (int s = 64; s; s >>= 1){ if (d < s) s_red[d] += s_red[d + s]; __syncthreads(); }
    if (d == 0){
        out[b*4 + 0] = tecs;
        out[b*4 + 1] = s_red[0];
        out[b*4 + 2] = duff[0]*duff[0]*delta_uff[b];
        out[b*4 + 3] = inter;
    }
}

// ---------------- launch ----------------
// d_in follows setup_inputs() dict insertion order:
//   0:h1 1:h2 2:adj1 3:dmv 4:charge1 5:charge2 6:vdw_epsilon 7:vdw_sigma
//   8:delta_uff 9:valid1 10:valid2 11:no_metal1 12:no_metal2 13:node_W
//   14:gat_W 15:gat_Wb 16:gat_A 17:gat_gW 18:gat_gb 19:pair_W1 20:pair_b1
//   21:pair_W2 22:pair_b2 23:vdw_coeff 24:duff_coeff 25:int_W1 26:int_b1
//   27:int_W2 28:int_b2
extern "C" void kernel_launch(void* const* d_in, const int* in_sizes, int n_in,
                              void* d_out, int out_size){
    const float* h1        = (const float*)d_in[0];
    const float* h2        = (const float*)d_in[1];
    const float* adj1      = (const float*)d_in[2];
    const float* dmv       = (const float*)d_in[3];
    const float* charge1   = (const float*)d_in[4];
    const float* charge2   = (const float*)d_in[5];
    const float* eps       = (const float*)d_in[6];
    const float* sig       = (const float*)d_in[7];
    const float* delta_uff = (const float*)d_in[8];
    const float* valid1    = (const float*)d_in[9];
    const float* valid2    = (const float*)d_in[10];
    const float* nm1       = (const float*)d_in[11];
    const float* nm2       = (const float*)d_in[12];
    const float* nodeW     = (const float*)d_in[13];
    const float* gatW      = (const float*)d_in[14];
    const float* gatWb     = (const float*)d_in[15];
    const float* gatA      = (const float*)d_in[16];
    const float* gatgW     = (const float*)d_in[17];
    const float* gatgb     = (const float*)d_in[18];
    const float* pW1       = (const float*)d_in[19];
    const float* pb1       = (const float*)d_in[20];
    const float* pW2       = (const float*)d_in[21];
    const float* pb2       = (const float*)d_in[22];
    const float* vdwc      = (const float*)d_in[23];
    const float* duffc     = (const float*)d_in[24];
    const float* iW1       = (const float*)d_in[25];
    const float* ib1       = (const float*)d_in[26];
    const float* iW2       = (const float*)d_in[27];
    const float* ib2       = (const float*)d_in[28];
    float* out = (float*)d_out;

    k_pre_node<<<LL*DD + (BB*(N1+N2))/4, 128>>>(gatW, gatWb, gatA, h1, h2, nodeW);
    k_stage2<<<96 + 240, 128>>>(gatW, gatWb, pW1);
    for (int l = 0; l < LL; l++){
        k_e    <<<dim3(N1/64, N1/32, BB), 256>>>(l & 1);
        k_stats<<<BB*N1/8, 256>>>(adj1);
        k_fuse <<<BB*N1/8, 256>>>(adj1, gatgW, gatgb, gatW, gatWb, pW1, pb1, l);
    }
    k_pair<<<dim3(N2/32, BB*N1/16), 256>>>(dmv, charge1, charge2, eps, sig,
                                           valid1, valid2, nm1, nm2, pW2, pb2, vdwc);
    k_final<<<BB, DD>>>(valid1, delta_uff, duffc, iW1, ib1, iW2, ib2, out);
}